// round 13
// baseline (speedup 1.0000x reference)
#include <cuda_runtime.h>
#include <math.h>

#define B_ 64
#define T_ 1024
#define I_ 128
#define H_ 512
#define O_ 128
#define GRID0 128
#define NT 512

typedef unsigned long long ull;

// ---- scratch (device globals: allocation-free) ----
__device__ float g_xT[T_ * I_ * B_];      // x transposed: [t][i][b]
__device__ float g_h0buf[2 * H_ * B_];    // layer0 h double buffer
__device__ float g_h1[T_ * H_ * B_];      // layer1 h history: [t][h][b]
__device__ unsigned g_bar_count;          // full gridbar (phase transitions)
__device__ unsigned g_bar_sense;
__device__ unsigned g_barA_cnt;           // split barrier A: protects h0
__device__ unsigned g_barA_sense;
__device__ unsigned g_barB_cnt;           // split barrier B: protects h1
__device__ unsigned g_barB_sense;

// ---- packed f32x2 helpers ----
__device__ __forceinline__ ull pack2(float x) {
    ull r; unsigned u = __float_as_uint(x);
    asm("mov.b64 %0, {%1, %1};" : "=l"(r) : "r"(u));
    return r;
}
__device__ __forceinline__ ull pack_ab(float a, float b) {
    ull r;
    asm("mov.b64 %0, {%1, %2};" : "=l"(r)
        : "r"(__float_as_uint(a)), "r"(__float_as_uint(b)));
    return r;
}
__device__ __forceinline__ void ffma2(ull &acc, ull a, ull w) {
    asm("fma.rn.f32x2 %0, %1, %2, %0;" : "+l"(acc) : "l"(a), "l"(w));
}
__device__ __forceinline__ ull addx2(ull a, ull b) {
    ull r;
    asm("add.rn.f32x2 %0, %1, %2;" : "=l"(r) : "l"(a), "l"(b));
    return r;
}
__device__ __forceinline__ float lo2(ull v) { return __uint_as_float((unsigned)v); }
__device__ __forceinline__ float hi2(ull v) { return __uint_as_float((unsigned)(v >> 32)); }

__device__ __forceinline__ float sigm(float x) {
    return __fdividef(1.f, 1.f + __expf(-x));
}
__device__ __forceinline__ float tanh_(float x) {
    return __fdividef(2.f, 1.f + __expf(-2.f * x)) - 1.f;
}

// ---- full grid barrier (phase transitions only) ----
__device__ __forceinline__ void gridbar(unsigned &sense) {
    __syncthreads();
    if (threadIdx.x == 0) {
        unsigned s = sense ^ 1u;
        sense = s;
        unsigned old;
        asm volatile("atom.release.gpu.global.add.u32 %0, [%1], %2;"
                     : "=r"(old) : "l"(&g_bar_count), "r"(1u));
        if (old == GRID0 - 1u) {
            g_bar_count = 0u;
            asm volatile("st.release.gpu.global.u32 [%0], %1;"
                         :: "l"(&g_bar_sense), "r"(s));
        } else {
            unsigned v;
            do {
                asm volatile("ld.acquire.gpu.global.u32 %0, [%1];"
                             : "=r"(v) : "l"(&g_bar_sense));
            } while (v != s);
        }
    }
    __syncthreads();
}

// ---- split barrier primitives (tid 0 only) ----
__device__ __forceinline__ void bar_arrive(unsigned* cnt, unsigned* sense, unsigned s) {
    unsigned old;
    asm volatile("atom.release.gpu.global.add.u32 %0, [%1], %2;"
                 : "=r"(old) : "l"(cnt), "r"(1u));
    if (old == GRID0 - 1u) {
        *cnt = 0u;
        asm volatile("st.release.gpu.global.u32 [%0], %1;" :: "l"(sense), "r"(s));
    }
}
__device__ __forceinline__ void bar_spin(unsigned* sense, unsigned s) {
    unsigned v;
    do {
        asm volatile("ld.acquire.gpu.global.u32 %0, [%1];" : "=r"(v) : "l"(sense));
    } while (v != s);
}

// ---- one 16-k block of Y-form FMAs: A (4 batches) x W (4 row-pairs) ----
__device__ __forceinline__ void fmaBlk(ull acc[16], float4 A, const float* wp) {
    ulonglong2 W01 = *(const ulonglong2*)wp;        // row-pairs 0,1
    ulonglong2 W23 = *(const ulonglong2*)(wp + 4);  // row-pairs 2,3
    ull A0 = pack2(A.x), A1 = pack2(A.y), A2 = pack2(A.z), A3 = pack2(A.w);
    ffma2(acc[0],  A0, W01.x); ffma2(acc[1],  A1, W01.x);
    ffma2(acc[2],  A2, W01.x); ffma2(acc[3],  A3, W01.x);
    ffma2(acc[4],  A0, W01.y); ffma2(acc[5],  A1, W01.y);
    ffma2(acc[6],  A2, W01.y); ffma2(acc[7],  A3, W01.y);
    ffma2(acc[8],  A0, W23.x); ffma2(acc[9],  A1, W23.x);
    ffma2(acc[10], A2, W23.x); ffma2(acc[11], A3, W23.x);
    ffma2(acc[12], A0, W23.y); ffma2(acc[13], A1, W23.y);
    ffma2(acc[14], A2, W23.y); ffma2(acc[15], A3, W23.y);
}

// ---- Y-form gate GEMM over one segment, 4-deep LDG pipeline ----
// Warp w handles k = blk*16 + w. Thread (bo, rg): rows rg*8..+7 (4 row-pairs),
// batches bo*4..+3. nblk is a multiple of 4 and >= 4 for all call sites.
__device__ __forceinline__ void gemmY(
    ull acc[16], const float* __restrict__ src, const float* __restrict__ Wt,
    int nblk, int w, int bo, int rg)
{
    const float* ap = src + w * B_ + bo * 4;
    const float* wp = Wt + w * 16 + rg * 8;
    const int S = 16 * B_;
    float4 A0 = __ldcg((const float4*)ap);
    float4 A1 = __ldcg((const float4*)(ap + S));
    float4 A2 = __ldcg((const float4*)(ap + 2 * S));
    float4 A3 = __ldcg((const float4*)(ap + 3 * S));
    int c = 0;
    for (; c + 4 < nblk; c += 4) {
        float4 N0 = __ldcg((const float4*)(ap + (c + 4) * S));
        fmaBlk(acc, A0, wp + c * 256);       A0 = N0;
        float4 N1 = __ldcg((const float4*)(ap + (c + 5) * S));
        fmaBlk(acc, A1, wp + (c + 1) * 256); A1 = N1;
        float4 N2 = __ldcg((const float4*)(ap + (c + 6) * S));
        fmaBlk(acc, A2, wp + (c + 2) * 256); A2 = N2;
        float4 N3 = __ldcg((const float4*)(ap + (c + 7) * S));
        fmaBlk(acc, A3, wp + (c + 3) * 256); A3 = N3;
    }
    fmaBlk(acc, A0, wp + c * 256);
    fmaBlk(acc, A1, wp + (c + 1) * 256);
    fmaBlk(acc, A2, wp + (c + 2) * 256);
    fmaBlk(acc, A3, wp + (c + 3) * 256);
}

// ---------------------------------------------------------------------------
// Mega kernel: transpose + both LSTM layers (pipelined) + FC, one launch.
__global__ void __launch_bounds__(NT, 1) mega_kernel(
    const float* __restrict__ x,
    const float* __restrict__ W_ih0, const float* __restrict__ W_hh0,
    const float* __restrict__ b_ih0, const float* __restrict__ b_hh0,
    const float* __restrict__ W_ih1, const float* __restrict__ W_hh1,
    const float* __restrict__ b_ih1, const float* __restrict__ b_hh1,
    const float* __restrict__ Wfc,  const float* __restrict__ bfc,
    float* __restrict__ out)
{
    extern __shared__ float sm[];
    float* Wt0   = sm;                 // [640][16]  = 10240 floats
    float* Wt1   = sm + 10240;         // [1024][16] = 16384 floats
    float* bias0 = sm + 26624;         // 16
    float* bias1 = sm + 26640;         // 16
    float* gs    = sm + 26656;         // 16 x 64    = 1024 floats
    ull*   red   = (ull*)(sm + 27680); // 16 warps * 512 ull = 65536 B

    const int tid = threadIdx.x;
    const int hj0 = blockIdx.x * 4;
    const int bo = tid & 15;
    const int rg = (tid >> 4) & 1;
    const int w  = tid >> 5;

    unsigned sense = 0, sAa = 0, sAw = 0, sBa = 0, sBw = 0;
    if (tid == 0) {
        sense = *(volatile unsigned*)&g_bar_sense;
        sAa = sAw = *(volatile unsigned*)&g_barA_sense;
        sBa = sBw = *(volatile unsigned*)&g_barB_sense;
    }

    // ---- transpose phase: x[b][t][i] -> g_xT[t][i][b] (tile in Wt1 region)
    {
        float (*tile)[I_ + 1] = (float (*)[I_ + 1])Wt1;   // 64 x 129 = 8256
        for (int t = blockIdx.x; t < T_; t += GRID0) {
            __syncthreads();
            for (int idx = tid; idx < B_ * I_; idx += NT) {
                int b = idx >> 7, i = idx & 127;
                tile[b][i] = x[(b * T_ + t) * I_ + i];
            }
            __syncthreads();
            for (int idx = tid; idx < B_ * I_; idx += NT) {
                int b = idx & 63, i = idx >> 6;
                g_xT[t * I_ * B_ + i * B_ + b] = tile[b][i];
            }
        }
    }
    gridbar(sense);

    // ---- transposed weight slices: Wt[k][r], r = gate*4 + c
    for (int idx = tid; idx < 640 * 16; idx += NT) {
        int k = idx >> 4, r = idx & 15;
        int grow = (r >> 2) * H_ + hj0 + (r & 3);
        Wt0[idx] = (k < I_) ? W_ih0[grow * I_ + k]
                            : W_hh0[grow * H_ + (k - I_)];
    }
    for (int idx = tid; idx < 1024 * 16; idx += NT) {
        int k = idx >> 4, r = idx & 15;
        int grow = (r >> 2) * H_ + hj0 + (r & 3);
        Wt1[idx] = (k < H_) ? W_ih1[grow * H_ + k]
                            : W_hh1[grow * H_ + (k - H_)];
    }
    if (tid < 16) {
        int grow = (tid >> 2) * H_ + hj0 + (tid & 3);
        bias0[tid] = b_ih0[grow] + b_hh0[grow];
        bias1[tid] = b_ih1[grow] + b_hh1[grow];
    }
    __syncthreads();

    // ---- main pipelined loop: layer0 at t=k, layer1 at s=k-1.
    // Split barriers: A guards h0 (arrive after layer1 consumed it, wait
    // before layer0's h0 segment); B guards h1 (arrive at iter end, wait
    // mid-layer1-GEMM). Both waits are buried under compute.
    float2 c0 = make_float2(0.f, 0.f), c1 = make_float2(0.f, 0.f);
    const int rp_u = tid >> 6;          // stage1 unit: row-pair 0..7
    const int b_u  = tid & 63;          //              batch 0..63
    const int c4_a = tid >> 5;          // act unit (tid<128): h-col 0..3
    const int bp_a = tid & 31;          //                      batch-pair

    for (int k = 0; k <= T_; ++k) {
        ull acc[16];

        // ===== layer 0 at t = k =====
        if (k < T_) {
#pragma unroll
            for (int i = 0; i < 16; i++) acc[i] = 0ull;
            gemmY(acc, g_xT + k * I_ * B_, Wt0, I_ / 16, w, bo, rg);   // x seg
        }
        if (k >= 1 && tid == 0) {           // h0[(k-1)&1] ready (barrier A)
            sAw ^= 1u;
            bar_spin(&g_barA_sense, sAw);
        }
        __syncthreads();
        if (k < T_ && k > 0)                // h0 segment
            gemmY(acc, g_h0buf + ((k - 1) & 1) * H_ * B_,
                  Wt0 + (I_ / 16) * 256, H_ / 16, w, bo, rg);
        __syncthreads();                    // red free (prev stage1_1 done)
        if (k < T_) {
            ull* rw = red + w * 512 + (rg * 4) * 64 + bo * 4;
#pragma unroll
            for (int rpl = 0; rpl < 4; rpl++) {
                *(ulonglong2*)(rw + rpl * 64)     =
                    make_ulonglong2(acc[rpl * 4 + 0], acc[rpl * 4 + 1]);
                *(ulonglong2*)(rw + rpl * 64 + 2) =
                    make_ulonglong2(acc[rpl * 4 + 2], acc[rpl * 4 + 3]);
            }
        }
        __syncthreads();
        if (k < T_) {                       // stage1: 512 threads, 1 unit each
            const ull* rr = red + rp_u * 64 + b_u;
            ull v = rr[0];
#pragma unroll
            for (int ww = 1; ww < 16; ww++) v = addx2(v, rr[ww * 512]);
            float2 bb = *(const float2*)(bias0 + 2 * rp_u);
            v = addx2(v, pack_ab(bb.x, bb.y));
            gs[(2 * rp_u) * 64 + b_u]     = lo2(v);
            gs[(2 * rp_u + 1) * 64 + b_u] = hi2(v);
        }
        __syncthreads();
        if (k < T_ && tid < 128) {          // act0 — overlaps GEMM1 below
            float2 xi = *(const float2*)(gs + (0  + c4_a) * 64 + 2 * bp_a);
            float2 xf = *(const float2*)(gs + (4  + c4_a) * 64 + 2 * bp_a);
            float2 xg = *(const float2*)(gs + (8  + c4_a) * 64 + 2 * bp_a);
            float2 xo = *(const float2*)(gs + (12 + c4_a) * 64 + 2 * bp_a);
            float i0 = sigm(xi.x), i1 = sigm(xi.y);
            float f0 = sigm(xf.x), f1 = sigm(xf.y);
            float g0 = tanh_(xg.x), g1 = tanh_(xg.y);
            float o0 = sigm(xo.x), o1 = sigm(xo.y);
            c0.x = f0 * c0.x + i0 * g0;
            c0.y = f1 * c0.y + i1 * g1;
            *(float2*)(g_h0buf + (k & 1) * H_ * B_ + hj0 * B_
                       + c4_a * B_ + 2 * bp_a) =
                make_float2(o0 * tanh_(c0.x), o1 * tanh_(c0.y));
        }

        // ===== layer 1 at s = k-1 =====
        if (k >= 1) {
#pragma unroll
            for (int i = 0; i < 16; i++) acc[i] = 0ull;
            gemmY(acc, g_h0buf + ((k - 1) & 1) * H_ * B_, Wt1,
                  H_ / 16, w, bo, rg);      // h0 segment
        }
        if (k >= 2 && tid == 0) {           // h1[k-2] ready (barrier B)
            sBw ^= 1u;
            bar_spin(&g_barB_sense, sBw);
        }
        __syncthreads();
        if (k >= 2)                         // h1 segment
            gemmY(acc, g_h1 + (k - 2) * H_ * B_,
                  Wt1 + (H_ / 16) * 256, H_ / 16, w, bo, rg);
        __syncthreads();                    // act0 + gemm1 complete
        if (k < T_ && tid == 0) {           // h0[k&1] written & consumed
            sAa ^= 1u;
            bar_arrive(&g_barA_cnt, &g_barA_sense, sAa);
        }
        if (k >= 1) {
            ull* rw = red + w * 512 + (rg * 4) * 64 + bo * 4;
#pragma unroll
            for (int rpl = 0; rpl < 4; rpl++) {
                *(ulonglong2*)(rw + rpl * 64)     =
                    make_ulonglong2(acc[rpl * 4 + 0], acc[rpl * 4 + 1]);
                *(ulonglong2*)(rw + rpl * 64 + 2) =
                    make_ulonglong2(acc[rpl * 4 + 2], acc[rpl * 4 + 3]);
            }
        }
        __syncthreads();
        if (k >= 1) {
            const ull* rr = red + rp_u * 64 + b_u;
            ull v = rr[0];
#pragma unroll
            for (int ww = 1; ww < 16; ww++) v = addx2(v, rr[ww * 512]);
            float2 bb = *(const float2*)(bias1 + 2 * rp_u);
            v = addx2(v, pack_ab(bb.x, bb.y));
            gs[(2 * rp_u) * 64 + b_u]     = lo2(v);
            gs[(2 * rp_u + 1) * 64 + b_u] = hi2(v);
        }
        __syncthreads();
        if (k >= 1 && tid < 128) {          // act1
            float2 xi = *(const float2*)(gs + (0  + c4_a) * 64 + 2 * bp_a);
            float2 xf = *(const float2*)(gs + (4  + c4_a) * 64 + 2 * bp_a);
            float2 xg = *(const float2*)(gs + (8  + c4_a) * 64 + 2 * bp_a);
            float2 xo = *(const float2*)(gs + (12 + c4_a) * 64 + 2 * bp_a);
            float i0 = sigm(xi.x), i1 = sigm(xi.y);
            float f0 = sigm(xf.x), f1 = sigm(xf.y);
            float g0 = tanh_(xg.x), g1 = tanh_(xg.y);
            float o0 = sigm(xo.x), o1 = sigm(xo.y);
            c1.x = f0 * c1.x + i0 * g0;
            c1.y = f1 * c1.y + i1 * g1;
            *(float2*)(g_h1 + (k - 1) * H_ * B_ + hj0 * B_
                       + c4_a * B_ + 2 * bp_a) =
                make_float2(o0 * tanh_(c1.x), o1 * tanh_(c1.y));
        }
        __syncthreads();                    // act1 writes complete CTA-wide
        if (k >= 1 && tid == 0) {           // h1[k-1] ready (barrier B)
            sBa ^= 1u;
            bar_arrive(&g_barB_cnt, &g_barB_sense, sBa);
        }
    }
    gridbar(sense);                         // all h1 globally complete

    // ---- FC phase: out[b][t][o] = sum_h h1[t][h][b] * Wfc[o][h] + bfc[o]
    {
        float* w_s = sm;                  // 128 x 65 = 8320
        float* h_s = sm + 8320;           // 64 x 64  = 4096
        float* o_s = sm + 12416;          // 64 x 128 = 8192
        const int ot = tid & 15;          // o = ot + j*16
        const int bt = (tid >> 4) & 15;   // batches bt*4 .. bt*4+3 (tid<256 only)

        for (int t = blockIdx.x; t < T_; t += GRID0) {
            ull acc[16];
#pragma unroll
            for (int i = 0; i < 16; i++) acc[i] = 0ull;

            for (int kb = 0; kb < H_; kb += 64) {
                __syncthreads();
                for (int idx = tid; idx < O_ * 64; idx += NT) {
                    int o = idx >> 6, kk = idx & 63;
                    w_s[o * 65 + kk] = Wfc[o * H_ + kb + kk];
                }
                for (int idx = tid; idx < 64 * B_; idx += NT) {
                    h_s[idx] = g_h1[(t * H_ + kb) * B_ + idx];
                }
                __syncthreads();
                if (tid < 256) {
#pragma unroll 4
                    for (int kk = 0; kk < 64; kk++) {
                        ulonglong2 A = *(const ulonglong2*)(h_s + kk * B_ + bt * 4);
#pragma unroll
                        for (int j = 0; j < 8; j++) {
                            ull ww = pack2(w_s[(ot + j * 16) * 65 + kk]);
                            ffma2(acc[j * 2 + 0], A.x, ww);
                            ffma2(acc[j * 2 + 1], A.y, ww);
                        }
                    }
                }
            }
            __syncthreads();
            if (tid < 256) {
#pragma unroll
                for (int j = 0; j < 8; j++) {
                    int o = ot + j * 16;
                    o_s[(bt * 4 + 0) * O_ + o] = lo2(acc[j * 2 + 0]);
                    o_s[(bt * 4 + 1) * O_ + o] = hi2(acc[j * 2 + 0]);
                    o_s[(bt * 4 + 2) * O_ + o] = lo2(acc[j * 2 + 1]);
                    o_s[(bt * 4 + 3) * O_ + o] = hi2(acc[j * 2 + 1]);
                }
            }
            __syncthreads();
            for (int idx = tid; idx < B_ * O_; idx += NT) {
                int b = idx >> 7, o = idx & 127;
                out[(b * T_ + t) * O_ + o] = o_s[idx] + __ldg(&bfc[o]);
            }
        }
    }
}

// ---------------------------------------------------------------------------
extern "C" void kernel_launch(void* const* d_in, const int* in_sizes, int n_in,
                              void* d_out, int out_size) {
    const float* x     = (const float*)d_in[0];
    const float* W_ih0 = (const float*)d_in[1];
    const float* W_hh0 = (const float*)d_in[2];
    const float* b_ih0 = (const float*)d_in[3];
    const float* b_hh0 = (const float*)d_in[4];
    const float* W_ih1 = (const float*)d_in[5];
    const float* W_hh1 = (const float*)d_in[6];
    const float* b_ih1 = (const float*)d_in[7];
    const float* b_hh1 = (const float*)d_in[8];
    const float* W_fc  = (const float*)d_in[9];
    const float* b_fc  = (const float*)d_in[10];
    float* out = (float*)d_out;

    size_t smem = (size_t)(27680 * 4 + 65536);   // 176256 B
    cudaFuncSetAttribute(mega_kernel, cudaFuncAttributeMaxDynamicSharedMemorySize, (int)smem);

    mega_kernel<<<GRID0, NT, smem>>>(x, W_ih0, W_hh0, b_ih0, b_hh0,
                                     W_ih1, W_hh1, b_ih1, b_hh1,
                                     W_fc, b_fc, out);
}

// round 14
// speedup vs baseline: 1.0848x; 1.0848x over previous
#include <cuda_runtime.h>
#include <math.h>

#define B_ 64
#define T_ 1024
#define I_ 128
#define H_ 512
#define O_ 128
#define GRID0 128
#define NT 512

typedef unsigned long long ull;

// ---- scratch (device globals: allocation-free) ----
__device__ float g_xT[T_ * I_ * B_];      // x transposed: [t][i][b]
__device__ float g_h0buf[2 * H_ * B_];    // layer0 h double buffer
__device__ float g_h1[T_ * H_ * B_];      // layer1 h history: [t][h][b]
__device__ unsigned g_bar_count;
__device__ unsigned g_bar_sense;

// ---- packed f32x2 helpers ----
__device__ __forceinline__ ull pack2(float x) {
    ull r; unsigned u = __float_as_uint(x);
    asm("mov.b64 %0, {%1, %1};" : "=l"(r) : "r"(u));
    return r;
}
__device__ __forceinline__ ull pack_ab(float a, float b) {
    ull r;
    asm("mov.b64 %0, {%1, %2};" : "=l"(r)
        : "r"(__float_as_uint(a)), "r"(__float_as_uint(b)));
    return r;
}
__device__ __forceinline__ void ffma2(ull &acc, ull a, ull w) {
    asm("fma.rn.f32x2 %0, %1, %2, %0;" : "+l"(acc) : "l"(a), "l"(w));
}
__device__ __forceinline__ ull addx2(ull a, ull b) {
    ull r;
    asm("add.rn.f32x2 %0, %1, %2;" : "=l"(r) : "l"(a), "l"(b));
    return r;
}
__device__ __forceinline__ float lo2(ull v) { return __uint_as_float((unsigned)v); }
__device__ __forceinline__ float hi2(ull v) { return __uint_as_float((unsigned)(v >> 32)); }

__device__ __forceinline__ float sigm(float x) {
    return __fdividef(1.f, 1.f + __expf(-x));
}
__device__ __forceinline__ float tanh_(float x) {
    return __fdividef(2.f, 1.f + __expf(-2.f * x)) - 1.f;
}

#define GBAR1() asm volatile("bar.sync 1, 256;" ::: "memory")
#define GBAR2() asm volatile("bar.sync 2, 256;" ::: "memory")

// ---- full grid barrier (identical to R12 passing kernel) ----
__device__ __forceinline__ void gridbar(unsigned &sense) {
    __syncthreads();
    if (threadIdx.x == 0) {
        unsigned s = sense ^ 1u;
        sense = s;
        unsigned old;
        asm volatile("atom.release.gpu.global.add.u32 %0, [%1], %2;"
                     : "=r"(old) : "l"(&g_bar_count), "r"(1u));
        if (old == GRID0 - 1u) {
            g_bar_count = 0u;
            asm volatile("st.release.gpu.global.u32 [%0], %1;"
                         :: "l"(&g_bar_sense), "r"(s));
        } else {
            unsigned v;
            do {
                asm volatile("ld.acquire.gpu.global.u32 %0, [%1];"
                             : "=r"(v) : "l"(&g_bar_sense));
            } while (v != s);
        }
    }
    __syncthreads();
}

// ---- one k of Y-form FMAs: A (4 batches) x W (4 row-pairs) ----
__device__ __forceinline__ void fmaBlk(ull acc[16], float4 A, const float* wp) {
    ulonglong2 W01 = *(const ulonglong2*)wp;        // row-pairs 0,1
    ulonglong2 W23 = *(const ulonglong2*)(wp + 4);  // row-pairs 2,3
    ull A0 = pack2(A.x), A1 = pack2(A.y), A2 = pack2(A.z), A3 = pack2(A.w);
    ffma2(acc[0],  A0, W01.x); ffma2(acc[1],  A1, W01.x);
    ffma2(acc[2],  A2, W01.x); ffma2(acc[3],  A3, W01.x);
    ffma2(acc[4],  A0, W01.y); ffma2(acc[5],  A1, W01.y);
    ffma2(acc[6],  A2, W01.y); ffma2(acc[7],  A3, W01.y);
    ffma2(acc[8],  A0, W23.x); ffma2(acc[9],  A1, W23.x);
    ffma2(acc[10], A2, W23.x); ffma2(acc[11], A3, W23.x);
    ffma2(acc[12], A0, W23.y); ffma2(acc[13], A1, W23.y);
    ffma2(acc[14], A2, W23.y); ffma2(acc[15], A3, W23.y);
}

// ---- Y-form gate GEMM, 8-warp group k-split, 4-deep LDG pipeline ----
// Group-warp wi handles k = wi + 8c. Thread (bo, rg): rows rg*8..+7 (4 row-
// pairs), batches bo*4..+3. nit is a multiple of 4 and >= 16 at all sites.
__device__ __forceinline__ void gemmY8(
    ull acc[16], const float* __restrict__ src, const float* __restrict__ Wt,
    int nit, int wi, int bo, int rg)
{
    const float* ap = src + wi * B_ + bo * 4;
    const float* wp = Wt + wi * 16 + rg * 8;
    const int S = 8 * B_;      // k stride (8 warps)
    const int WS = 8 * 16;     // Wt stride per k step
    float4 A0 = __ldcg((const float4*)ap);
    float4 A1 = __ldcg((const float4*)(ap + S));
    float4 A2 = __ldcg((const float4*)(ap + 2 * S));
    float4 A3 = __ldcg((const float4*)(ap + 3 * S));
    int c = 0;
    for (; c + 4 < nit; c += 4) {
        float4 N0 = __ldcg((const float4*)(ap + (c + 4) * S));
        fmaBlk(acc, A0, wp + c * WS);       A0 = N0;
        float4 N1 = __ldcg((const float4*)(ap + (c + 5) * S));
        fmaBlk(acc, A1, wp + (c + 1) * WS); A1 = N1;
        float4 N2 = __ldcg((const float4*)(ap + (c + 6) * S));
        fmaBlk(acc, A2, wp + (c + 2) * WS); A2 = N2;
        float4 N3 = __ldcg((const float4*)(ap + (c + 7) * S));
        fmaBlk(acc, A3, wp + (c + 3) * WS); A3 = N3;
    }
    fmaBlk(acc, A0, wp + c * WS);
    fmaBlk(acc, A1, wp + (c + 1) * WS);
    fmaBlk(acc, A2, wp + (c + 2) * WS);
    fmaBlk(acc, A3, wp + (c + 3) * WS);
}

// ---------------------------------------------------------------------------
// Mega kernel: transpose + both LSTM layers (warp-specialized) + FC.
__global__ void __launch_bounds__(NT, 1) mega_kernel(
    const float* __restrict__ x,
    const float* __restrict__ W_ih0, const float* __restrict__ W_hh0,
    const float* __restrict__ b_ih0, const float* __restrict__ b_hh0,
    const float* __restrict__ W_ih1, const float* __restrict__ W_hh1,
    const float* __restrict__ b_ih1, const float* __restrict__ b_hh1,
    const float* __restrict__ Wfc,  const float* __restrict__ bfc,
    float* __restrict__ out)
{
    extern __shared__ float sm[];
    float* Wt0   = sm;                 // [640][16]  = 10240 floats
    float* Wt1   = sm + 10240;         // [1024][16] = 16384 floats
    float* bias0 = sm + 26624;         // 16
    float* bias1 = sm + 26640;         // 16
    float* gs0   = sm + 26656;         // 16 x 64 = 1024
    float* gs1   = sm + 27680;         // 16 x 64 = 1024
    ull*   red   = (ull*)(sm + 28704); // 2 groups * 8 warps * 512 ull = 64KB

    const int tid  = threadIdx.x;
    const int hj0  = blockIdx.x * 4;
    const int grp  = tid >> 8;         // 0: layer0, 1: layer1
    const int gtid = tid & 255;
    const int bo   = gtid & 15;
    const int rg   = (gtid >> 4) & 1;
    const int wi   = gtid >> 5;        // group-warp 0..7

    unsigned sense = 0;
    if (tid == 0) sense = *(volatile unsigned*)&g_bar_sense;

    // ---- transpose phase: x[b][t][i] -> g_xT[t][i][b] (tile in Wt1 region)
    {
        float (*tile)[I_ + 1] = (float (*)[I_ + 1])Wt1;   // 64 x 129 = 8256
        for (int t = blockIdx.x; t < T_; t += GRID0) {
            __syncthreads();
            for (int idx = tid; idx < B_ * I_; idx += NT) {
                int b = idx >> 7, i = idx & 127;
                tile[b][i] = x[(b * T_ + t) * I_ + i];
            }
            __syncthreads();
            for (int idx = tid; idx < B_ * I_; idx += NT) {
                int b = idx & 63, i = idx >> 6;
                g_xT[t * I_ * B_ + i * B_ + b] = tile[b][i];
            }
        }
    }
    gridbar(sense);

    // ---- transposed weight slices: Wt[k][r], r = gate*4 + c
    for (int idx = tid; idx < 640 * 16; idx += NT) {
        int k = idx >> 4, r = idx & 15;
        int grow = (r >> 2) * H_ + hj0 + (r & 3);
        Wt0[idx] = (k < I_) ? W_ih0[grow * I_ + k]
                            : W_hh0[grow * H_ + (k - I_)];
    }
    for (int idx = tid; idx < 1024 * 16; idx += NT) {
        int k = idx >> 4, r = idx & 15;
        int grow = (r >> 2) * H_ + hj0 + (r & 3);
        Wt1[idx] = (k < H_) ? W_ih1[grow * H_ + k]
                            : W_hh1[grow * H_ + (k - H_)];
    }
    if (tid < 16) {
        int grow = (tid >> 2) * H_ + hj0 + (tid & 3);
        bias0[tid] = b_ih0[grow] + b_hh0[grow];
        bias1[tid] = b_ih1[grow] + b_hh1[grow];
    }
    __syncthreads();

    // ---- main loop: group0 does layer0 at t=k, group1 does layer1 at s=k-1,
    //      CONCURRENTLY. Group-local named barriers; one gridbar per iter.
    float2 cst = make_float2(0.f, 0.f);
    ull* redG    = red + grp * 4096;
    float* gsG   = grp ? gs1 : gs0;
    float* biasG = grp ? bias1 : bias0;
    const int c4_a = gtid >> 5;        // act unit (gtid<128): h-col 0..3
    const int bp_a = gtid & 31;        //                      batch-pair

    for (int k = 0; k <= T_; ++k) {
        const bool active = grp ? (k >= 1) : (k < T_);
        if (active) {
            ull acc[16];
#pragma unroll
            for (int i = 0; i < 16; i++) acc[i] = 0ull;

            if (grp == 0) {
                gemmY8(acc, g_xT + k * I_ * B_, Wt0, 16, wi, bo, rg);
                if (k > 0)
                    gemmY8(acc, g_h0buf + ((k - 1) & 1) * H_ * B_,
                           Wt0 + I_ * 16, 64, wi, bo, rg);
            } else {
                gemmY8(acc, g_h0buf + ((k - 1) & 1) * H_ * B_,
                       Wt1, 64, wi, bo, rg);
                if (k >= 2)
                    gemmY8(acc, g_h1 + (k - 2) * H_ * B_,
                           Wt1 + H_ * 16, 64, wi, bo, rg);
            }

            // dump partials (red freed by last iter's gridbar)
            {
                ull* rw = redG + wi * 512 + (rg * 4) * 64 + bo * 4;
#pragma unroll
                for (int rpl = 0; rpl < 4; rpl++) {
                    *(ulonglong2*)(rw + rpl * 64)     =
                        make_ulonglong2(acc[rpl * 4 + 0], acc[rpl * 4 + 1]);
                    *(ulonglong2*)(rw + rpl * 64 + 2) =
                        make_ulonglong2(acc[rpl * 4 + 2], acc[rpl * 4 + 3]);
                }
            }
            if (grp == 0) GBAR1(); else GBAR2();

            // stage1: 256 threads, 2 units each (unit = row-pair x batch)
#pragma unroll
            for (int uu = 0; uu < 2; uu++) {
                int u = gtid + uu * 256;
                int rp = u >> 6, b = u & 63;
                const ull* rr = redG + rp * 64 + b;
                ull v = rr[0];
#pragma unroll
                for (int ww = 1; ww < 8; ww++) v = addx2(v, rr[ww * 512]);
                float2 bb = *(const float2*)(biasG + 2 * rp);
                v = addx2(v, pack_ab(bb.x, bb.y));
                gsG[(2 * rp) * 64 + b]     = lo2(v);
                gsG[(2 * rp + 1) * 64 + b] = hi2(v);
            }
            if (grp == 0) GBAR1(); else GBAR2();

            // activation: 128 threads of the group
            if (gtid < 128) {
                float2 xi = *(const float2*)(gsG + (0  + c4_a) * 64 + 2 * bp_a);
                float2 xf = *(const float2*)(gsG + (4  + c4_a) * 64 + 2 * bp_a);
                float2 xg = *(const float2*)(gsG + (8  + c4_a) * 64 + 2 * bp_a);
                float2 xo = *(const float2*)(gsG + (12 + c4_a) * 64 + 2 * bp_a);
                float i0 = sigm(xi.x), i1 = sigm(xi.y);
                float f0 = sigm(xf.x), f1 = sigm(xf.y);
                float g0 = tanh_(xg.x), g1 = tanh_(xg.y);
                float o0 = sigm(xo.x), o1 = sigm(xo.y);
                cst.x = f0 * cst.x + i0 * g0;
                cst.y = f1 * cst.y + i1 * g1;
                float* hdst = grp
                    ? (g_h1 + (k - 1) * H_ * B_ + hj0 * B_)
                    : (g_h0buf + (k & 1) * H_ * B_ + hj0 * B_);
                *(float2*)(hdst + c4_a * B_ + 2 * bp_a) =
                    make_float2(o0 * tanh_(cst.x), o1 * tanh_(cst.y));
            }
        }
        gridbar(sense);
    }

    // ---- FC phase: out[b][t][o] = sum_h h1[t][h][b] * Wfc[o][h] + bfc[o]
    {
        float* w_s = sm;                  // 128 x 65 = 8320
        float* h_s = sm + 8320;           // 64 x 64  = 4096
        float* o_s = sm + 12416;          // 64 x 128 = 8192
        const int ot = tid & 15;          // o = ot + j*16
        const int bt = (tid >> 4) & 15;   // batches bt*4..+3 (tid<256 only)

        for (int t = blockIdx.x; t < T_; t += GRID0) {
            ull acc[16];
#pragma unroll
            for (int i = 0; i < 16; i++) acc[i] = 0ull;

            for (int kb = 0; kb < H_; kb += 64) {
                __syncthreads();
                for (int idx = tid; idx < O_ * 64; idx += NT) {
                    int o = idx >> 6, kk = idx & 63;
                    w_s[o * 65 + kk] = Wfc[o * H_ + kb + kk];
                }
                for (int idx = tid; idx < 64 * B_; idx += NT) {
                    h_s[idx] = g_h1[(t * H_ + kb) * B_ + idx];
                }
                __syncthreads();
                if (tid < 256) {
#pragma unroll 4
                    for (int kk = 0; kk < 64; kk++) {
                        ulonglong2 A = *(const ulonglong2*)(h_s + kk * B_ + bt * 4);
#pragma unroll
                        for (int j = 0; j < 8; j++) {
                            ull ww = pack2(w_s[(ot + j * 16) * 65 + kk]);
                            ffma2(acc[j * 2 + 0], A.x, ww);
                            ffma2(acc[j * 2 + 1], A.y, ww);
                        }
                    }
                }
            }
            __syncthreads();
            if (tid < 256) {
#pragma unroll
                for (int j = 0; j < 8; j++) {
                    int o = ot + j * 16;
                    o_s[(bt * 4 + 0) * O_ + o] = lo2(acc[j * 2 + 0]);
                    o_s[(bt * 4 + 1) * O_ + o] = hi2(acc[j * 2 + 0]);
                    o_s[(bt * 4 + 2) * O_ + o] = lo2(acc[j * 2 + 1]);
                    o_s[(bt * 4 + 3) * O_ + o] = hi2(acc[j * 2 + 1]);
                }
            }
            __syncthreads();
            for (int idx = tid; idx < B_ * O_; idx += NT) {
                int b = idx >> 7, o = idx & 127;
                out[(b * T_ + t) * O_ + o] = o_s[idx] + __ldg(&bfc[o]);
            }
        }
    }
}

// ---------------------------------------------------------------------------
extern "C" void kernel_launch(void* const* d_in, const int* in_sizes, int n_in,
                              void* d_out, int out_size) {
    const float* x     = (const float*)d_in[0];
    const float* W_ih0 = (const float*)d_in[1];
    const float* W_hh0 = (const float*)d_in[2];
    const float* b_ih0 = (const float*)d_in[3];
    const float* b_hh0 = (const float*)d_in[4];
    const float* W_ih1 = (const float*)d_in[5];
    const float* W_hh1 = (const float*)d_in[6];
    const float* b_ih1 = (const float*)d_in[7];
    const float* b_hh1 = (const float*)d_in[8];
    const float* W_fc  = (const float*)d_in[9];
    const float* b_fc  = (const float*)d_in[10];
    float* out = (float*)d_out;

    size_t smem = (size_t)(28704 * 4 + 65536);   // 180352 B
    cudaFuncSetAttribute(mega_kernel, cudaFuncAttributeMaxDynamicSharedMemorySize, (int)smem);

    mega_kernel<<<GRID0, NT, smem>>>(x, W_ih0, W_hh0, b_ih0, b_hh0,
                                     W_ih1, W_hh1, b_ih1, b_hh1,
                                     W_fc, b_fc, out);
}